// round 1
// baseline (speedup 1.0000x reference)
#include <cuda_runtime.h>
#include <math.h>

#define Bz 2
#define Sz 2048
#define Dz 1024
#define Hz 16
#define HDz 64

// ---------------- scratch (device globals; no allocation allowed) ----------
__device__ float g_ln[Bz * Sz * Dz];            // layernorm output (reused for ln1, ln2)
__device__ float g_c[Bz * Sz * 3 * Dz];         // qkv gemm output
__device__ float g_q[Bz * Hz * Sz * HDz];       // q in [B,H,S,hd]
__device__ float g_a[Bz * Sz * Dz];             // attention output in [B,S,D]
__device__ float g_xa[Bz * Sz * Dz];            // x + attn
__device__ float g_h1[Bz * Sz * 4 * Dz];        // mlp hidden

// ---------------- layernorm: one block per row, D=1024 ---------------------
__global__ void layernorm_k(const float* __restrict__ x, const float* __restrict__ g,
                            const float* __restrict__ b, float* __restrict__ y) {
    int row = blockIdx.x;
    int tid = threadIdx.x;                       // 256 threads
    const float4* xr = (const float4*)(x + (size_t)row * Dz);
    float4 v = xr[tid];
    float s  = v.x + v.y + v.z + v.w;
    float sq = v.x * v.x + v.y * v.y + v.z * v.z + v.w * v.w;

    __shared__ float shs[8], shq[8];
    for (int o = 16; o; o >>= 1) { s += __shfl_xor_sync(0xffffffffu, s, o); sq += __shfl_xor_sync(0xffffffffu, sq, o); }
    int lane = tid & 31, wid = tid >> 5;
    if (lane == 0) { shs[wid] = s; shq[wid] = sq; }
    __syncthreads();
    float ts = 0.f, tq = 0.f;
    #pragma unroll
    for (int i = 0; i < 8; i++) { ts += shs[i]; tq += shq[i]; }
    float mean = ts * (1.0f / Dz);
    float var  = tq * (1.0f / Dz) - mean * mean;
    float rstd = rsqrtf(var + 1e-5f);

    float4 gg = ((const float4*)g)[tid];
    float4 bb = ((const float4*)b)[tid];
    float4 o;
    o.x = (v.x - mean) * rstd * gg.x + bb.x;
    o.y = (v.y - mean) * rstd * gg.y + bb.y;
    o.z = (v.z - mean) * rstd * gg.z + bb.z;
    o.w = (v.w - mean) * rstd * gg.w + bb.w;
    ((float4*)(y + (size_t)row * Dz))[tid] = o;
}

// ---------------- generic SGEMM: C = A@B + bias (+res | gelu) --------------
// A [M,K] row-major lda, B [K,N] row-major ldb, C [M,N] ldc. BM=BN=128, BK=8.
// EPI: 0 = bias, 1 = bias + residual, 2 = bias then exact GELU
template <int EPI>
__global__ void sgemm128(const float* __restrict__ A, const float* __restrict__ B,
                         const float* __restrict__ bias, const float* __restrict__ res,
                         float* __restrict__ C, int M, int N, int K,
                         int lda, int ldb, int ldc) {
    __shared__ float As[8][128];
    __shared__ float Bs[8][128];
    int row0 = blockIdx.y * 128, col0 = blockIdx.x * 128;
    int tid = threadIdx.x;
    int tx = tid & 15, ty = tid >> 4;

    int aRow = tid >> 1;            // 0..127
    int aCol = (tid & 1) * 4;       // 0 or 4
    int bRow = tid >> 5;            // 0..7
    int bCol = (tid & 31) * 4;      // 0..124

    const float* Aptr = A + (size_t)(row0 + aRow) * lda + aCol;
    const float* Bptr = B + (size_t)bRow * ldb + col0 + bCol;

    float acc[8][8];
    #pragma unroll
    for (int i = 0; i < 8; i++)
        #pragma unroll
        for (int j = 0; j < 8; j++) acc[i][j] = 0.f;

    for (int k0 = 0; k0 < K; k0 += 8) {
        float4 a4 = *(const float4*)(Aptr + k0);
        float4 b4 = *(const float4*)(Bptr + (size_t)k0 * ldb);
        As[aCol + 0][aRow] = a4.x;
        As[aCol + 1][aRow] = a4.y;
        As[aCol + 2][aRow] = a4.z;
        As[aCol + 3][aRow] = a4.w;
        *(float4*)&Bs[bRow][bCol] = b4;
        __syncthreads();
        #pragma unroll
        for (int k = 0; k < 8; k++) {
            float ra[8], rb[8];
            *(float4*)&ra[0] = *(const float4*)&As[k][ty * 8];
            *(float4*)&ra[4] = *(const float4*)&As[k][ty * 8 + 4];
            *(float4*)&rb[0] = *(const float4*)&Bs[k][tx * 8];
            *(float4*)&rb[4] = *(const float4*)&Bs[k][tx * 8 + 4];
            #pragma unroll
            for (int i = 0; i < 8; i++)
                #pragma unroll
                for (int j = 0; j < 8; j++) acc[i][j] = fmaf(ra[i], rb[j], acc[i][j]);
        }
        __syncthreads();
    }

    #pragma unroll
    for (int i = 0; i < 8; i++) {
        int r = row0 + ty * 8 + i;
        #pragma unroll
        for (int j = 0; j < 8; j++) {
            int c = col0 + tx * 8 + j;
            float v = acc[i][j] + bias[c];
            if (EPI == 1) v += res[(size_t)r * ldc + c];
            if (EPI == 2) v = 0.5f * v * (1.0f + erff(v * 0.70710678118654752f));
            C[(size_t)r * ldc + c] = v;
        }
    }
}

// ---------------- scatter qkv: c[4096,3072] -> q scratch + present out -----
__global__ void scatter_qkv(const float* __restrict__ c, float* __restrict__ q,
                            float* __restrict__ present) {
    int idx = blockIdx.x * blockDim.x + threadIdx.x;
    if (idx >= Bz * Sz * 3 * Dz) return;
    int row = idx / (3 * Dz);
    int col = idx - row * (3 * Dz);
    int b = row >> 11, s = row & (Sz - 1);
    int which = col >> 10;
    int rest = col & (Dz - 1);
    int h = rest >> 6, d = rest & 63;
    float val = c[idx];
    if (which == 0)
        q[(((size_t)(b * Hz + h) * Sz + s) * HDz) + d] = val;
    else
        present[(((size_t)((b * 2 + (which - 1)) * Hz + h) * Sz + s) * HDz) + d] = val;
}

// ---------------- scores: W = scale * Q @ K^T (NT), per (b,h) --------------
__global__ void scores_k(const float* __restrict__ q, const float* __restrict__ present,
                         float* __restrict__ w) {
    int bh = blockIdx.z;
    int row0 = blockIdx.y * 64, col0 = blockIdx.x * 64;
    if (col0 > row0 + 63) return;               // fully masked block
    int b = bh >> 4, h = bh & 15;
    const float* Q  = q + (size_t)bh * Sz * HDz;
    const float* Kd = present + (size_t)((b * 2) * Hz + h) * Sz * HDz;
    float* W = w + (size_t)bh * Sz * Sz;

    __shared__ float Qs[64][65];
    __shared__ float Ks[64][65];
    int tid = threadIdx.x;
    int r = tid >> 4, c4 = (tid & 15) * 4;
    #pragma unroll
    for (int rr = r; rr < 64; rr += 16) {
        float4 a = *(const float4*)(Q + (size_t)(row0 + rr) * HDz + c4);
        Qs[rr][c4 + 0] = a.x; Qs[rr][c4 + 1] = a.y; Qs[rr][c4 + 2] = a.z; Qs[rr][c4 + 3] = a.w;
        float4 k4 = *(const float4*)(Kd + (size_t)(col0 + rr) * HDz + c4);
        Ks[rr][c4 + 0] = k4.x; Ks[rr][c4 + 1] = k4.y; Ks[rr][c4 + 2] = k4.z; Ks[rr][c4 + 3] = k4.w;
    }
    __syncthreads();

    int tx = tid & 15, ty = tid >> 4;
    float acc[4][4];
    #pragma unroll
    for (int i = 0; i < 4; i++)
        #pragma unroll
        for (int j = 0; j < 4; j++) acc[i][j] = 0.f;

    #pragma unroll
    for (int d = 0; d < 64; d++) {
        float ra[4], rb[4];
        #pragma unroll
        for (int i = 0; i < 4; i++) ra[i] = Qs[ty * 4 + i][d];
        #pragma unroll
        for (int j = 0; j < 4; j++) rb[j] = Ks[tx * 4 + j][d];
        #pragma unroll
        for (int i = 0; i < 4; i++)
            #pragma unroll
            for (int j = 0; j < 4; j++) acc[i][j] = fmaf(ra[i], rb[j], acc[i][j]);
    }
    #pragma unroll
    for (int i = 0; i < 4; i++)
        #pragma unroll
        for (int j = 0; j < 4; j++)
            W[(size_t)(row0 + ty * 4 + i) * Sz + col0 + tx * 4 + j] = acc[i][j] * 0.125f;
}

// ---------------- causal softmax, in place on w ----------------------------
__global__ void softmax_causal(float* __restrict__ w) {
    int row = blockIdx.x;
    int bh  = blockIdx.y;
    float* wr = w + ((size_t)bh * Sz + row) * Sz;
    int n = row + 1;
    int tid = threadIdx.x;
    __shared__ float sh[8];
    int lane = tid & 31, wid = tid >> 5;

    float m = -1e30f;
    for (int j = tid; j < n; j += 256) m = fmaxf(m, wr[j]);
    for (int o = 16; o; o >>= 1) m = fmaxf(m, __shfl_xor_sync(0xffffffffu, m, o));
    if (lane == 0) sh[wid] = m;
    __syncthreads();
    float M = -1e30f;
    #pragma unroll
    for (int i = 0; i < 8; i++) M = fmaxf(M, sh[i]);
    __syncthreads();

    float s = 0.f;
    for (int j = tid; j < n; j += 256) s += expf(wr[j] - M);
    for (int o = 16; o; o >>= 1) s += __shfl_xor_sync(0xffffffffu, s, o);
    if (lane == 0) sh[wid] = s;
    __syncthreads();
    float Ssum = 0.f;
    #pragma unroll
    for (int i = 0; i < 8; i++) Ssum += sh[i];
    float inv = 1.0f / Ssum;

    for (int j = tid; j < Sz; j += 256)
        wr[j] = (j < n) ? expf(wr[j] - M) * inv : 0.0f;
}

// ---------------- A = W @ V per (b,h), causal K trimming -------------------
__global__ void av_gemm(const float* __restrict__ w, const float* __restrict__ present,
                        float* __restrict__ a) {
    int bh = blockIdx.z;
    int b = bh >> 4, h = bh & 15;
    int row0 = blockIdx.y * 64;
    const float* W = w + (size_t)bh * Sz * Sz;
    const float* V = present + (size_t)((b * 2 + 1) * Hz + h) * Sz * HDz;
    float* A = a + ((size_t)b * Sz) * Dz + h * HDz;

    __shared__ float Ws[16][65];
    __shared__ float Vs[16][64];
    int tid = threadIdx.x;
    int aR = tid >> 2, aC = (tid & 3) * 4;      // 64 x 16 tile of W
    int bR = tid >> 4, bC = (tid & 15) * 4;     // 16 x 64 tile of V
    int tx = tid & 15, ty = tid >> 4;

    float acc[4][4];
    #pragma unroll
    for (int i = 0; i < 4; i++)
        #pragma unroll
        for (int j = 0; j < 4; j++) acc[i][j] = 0.f;

    int kEnd = row0 + 64;                       // w[row, k>row] == 0 (causal)
    for (int k0 = 0; k0 < kEnd; k0 += 16) {
        float4 wv = *(const float4*)(W + (size_t)(row0 + aR) * Sz + k0 + aC);
        Ws[aC + 0][aR] = wv.x; Ws[aC + 1][aR] = wv.y; Ws[aC + 2][aR] = wv.z; Ws[aC + 3][aR] = wv.w;
        *(float4*)&Vs[bR][bC] = *(const float4*)(V + (size_t)(k0 + bR) * HDz + bC);
        __syncthreads();
        #pragma unroll
        for (int k = 0; k < 16; k++) {
            float ra[4], rb[4];
            #pragma unroll
            for (int i = 0; i < 4; i++) ra[i] = Ws[k][ty * 4 + i];
            #pragma unroll
            for (int j = 0; j < 4; j++) rb[j] = Vs[k][tx * 4 + j];
            #pragma unroll
            for (int i = 0; i < 4; i++)
                #pragma unroll
                for (int j = 0; j < 4; j++) acc[i][j] = fmaf(ra[i], rb[j], acc[i][j]);
        }
        __syncthreads();
    }
    #pragma unroll
    for (int i = 0; i < 4; i++)
        #pragma unroll
        for (int j = 0; j < 4; j++)
            A[(size_t)(row0 + ty * 4 + i) * Dz + tx * 4 + j] = acc[i][j];
}

// ---------------- host ------------------------------------------------------
extern "C" void kernel_launch(void* const* d_in, const int* in_sizes, int n_in,
                              void* d_out, int out_size) {
    const float* x       = (const float*)d_in[0];
    const float* qkv_w   = (const float*)d_in[1];
    const float* qkv_b   = (const float*)d_in[2];
    const float* merge_w = (const float*)d_in[3];
    const float* merge_b = (const float*)d_in[4];
    const float* mlp1_w  = (const float*)d_in[5];
    const float* mlp1_b  = (const float*)d_in[6];
    const float* mlp2_w  = (const float*)d_in[7];
    const float* mlp2_b  = (const float*)d_in[8];
    const float* n1_g    = (const float*)d_in[9];
    const float* n1_b    = (const float*)d_in[10];
    const float* n2_g    = (const float*)d_in[11];
    const float* n2_b    = (const float*)d_in[12];

    float *ln, *c, *q, *a, *xa, *h1;
    cudaGetSymbolAddress((void**)&ln, g_ln);
    cudaGetSymbolAddress((void**)&c,  g_c);
    cudaGetSymbolAddress((void**)&q,  g_q);
    cudaGetSymbolAddress((void**)&a,  g_a);
    cudaGetSymbolAddress((void**)&xa, g_xa);
    cudaGetSymbolAddress((void**)&h1, g_h1);

    float* out     = (float*)d_out;
    float* xm      = out;                                   // [B,S,D]
    float* present = out + (size_t)Bz * Sz * Dz;            // [B,2,H,S,hd]
    float* w       = present + (size_t)Bz * 2 * Hz * Sz * HDz; // [B,H,S,S]

    const int M = Bz * Sz;   // 4096

    // 1) ln1
    layernorm_k<<<M, 256>>>(x, n1_g, n1_b, ln);
    // 2) qkv gemm
    sgemm128<0><<<dim3(3 * Dz / 128, M / 128), 256>>>(ln, qkv_w, qkv_b, nullptr, c,
                                                      M, 3 * Dz, Dz, Dz, 3 * Dz, 3 * Dz);
    // 3) scatter q -> scratch, k/v -> present (output)
    scatter_qkv<<<(M * 3 * Dz) / 256, 256>>>(c, q, present);
    // 4) scores (causal-trimmed) -> w region
    scores_k<<<dim3(Sz / 64, Sz / 64, Bz * Hz), 256>>>(q, present, w);
    // 5) causal softmax in place on w
    softmax_causal<<<dim3(Sz, Bz * Hz), 256>>>(w);
    // 6) attn out = w @ v  -> g_a in [B,S,D] layout
    av_gemm<<<dim3(1, Sz / 64, Bz * Hz), 256>>>(w, present, a);
    // 7) merge gemm + residual -> xa
    sgemm128<1><<<dim3(Dz / 128, M / 128), 256>>>(a, merge_w, merge_b, x, xa,
                                                  M, Dz, Dz, Dz, Dz, Dz);
    // 8) ln2
    layernorm_k<<<M, 256>>>(xa, n2_g, n2_b, ln);
    // 9) mlp1 + gelu
    sgemm128<2><<<dim3(4 * Dz / 128, M / 128), 256>>>(ln, mlp1_w, mlp1_b, nullptr, h1,
                                                      M, 4 * Dz, Dz, Dz, 4 * Dz, 4 * Dz);
    // 10) mlp2 + residual -> xm (output)
    sgemm128<1><<<dim3(Dz / 128, M / 128), 256>>>(h1, mlp2_w, mlp2_b, xa, xm,
                                                  M, Dz, 4 * Dz, 4 * Dz, Dz, Dz);
}

// round 2
// speedup vs baseline: 2.0461x; 2.0461x over previous
#include <cuda_runtime.h>
#include <math.h>
#include <stdint.h>

#define Bz 2
#define Sz 2048
#define Dz 1024
#define Hz 16
#define HDz 64

// ---------------- scratch (device globals; no allocation allowed) ----------
__device__ float g_ln[Bz * Sz * Dz];            // layernorm output (reused for ln1, ln2)
__device__ float g_c[Bz * Sz * 3 * Dz];         // qkv gemm output
__device__ float g_q[Bz * Hz * Sz * HDz];       // q in [B,H,S,hd]
__device__ float g_a[Bz * Sz * Dz];             // attention output in [B,S,D]
__device__ float g_xa[Bz * Sz * Dz];            // x + attn
__device__ float g_h1[Bz * Sz * 4 * Dz];        // mlp hidden

// ---------------- layernorm: one block per row, D=1024 ---------------------
__global__ void layernorm_k(const float* __restrict__ x, const float* __restrict__ g,
                            const float* __restrict__ b, float* __restrict__ y) {
    int row = blockIdx.x;
    int tid = threadIdx.x;                       // 256 threads
    const float4* xr = (const float4*)(x + (size_t)row * Dz);
    float4 v = xr[tid];
    float s  = v.x + v.y + v.z + v.w;
    float sq = v.x * v.x + v.y * v.y + v.z * v.z + v.w * v.w;

    __shared__ float shs[8], shq[8];
    for (int o = 16; o; o >>= 1) { s += __shfl_xor_sync(0xffffffffu, s, o); sq += __shfl_xor_sync(0xffffffffu, sq, o); }
    int lane = tid & 31, wid = tid >> 5;
    if (lane == 0) { shs[wid] = s; shq[wid] = sq; }
    __syncthreads();
    float ts = 0.f, tq = 0.f;
    #pragma unroll
    for (int i = 0; i < 8; i++) { ts += shs[i]; tq += shq[i]; }
    float mean = ts * (1.0f / Dz);
    float var  = tq * (1.0f / Dz) - mean * mean;
    float rstd = rsqrtf(var + 1e-5f);

    float4 gg = ((const float4*)g)[tid];
    float4 bb = ((const float4*)b)[tid];
    float4 o;
    o.x = (v.x - mean) * rstd * gg.x + bb.x;
    o.y = (v.y - mean) * rstd * gg.y + bb.y;
    o.z = (v.z - mean) * rstd * gg.z + bb.z;
    o.w = (v.w - mean) * rstd * gg.w + bb.w;
    ((float4*)(y + (size_t)row * Dz))[tid] = o;
}

// ---------------- tf32 tensor-core GEMM ------------------------------------
// C = A@B + bias (+res | gelu). A [M,K] lda, B [K,N] ldb row-major, C ldc.
// BM=128, BN=128, BK=32; 8 warps (2x4), each warp 64x32 via m16n8k8 tf32 mma.
__device__ __forceinline__ uint32_t f2tf32(float x) {
    uint32_t y;
    asm("cvt.rna.tf32.f32 %0, %1;" : "=r"(y) : "f"(x));
    return y;
}

__device__ __forceinline__ void mma_tf32(float (&d)[4], const uint32_t (&a)[4], const uint32_t (&b)[2]) {
    asm volatile("mma.sync.aligned.m16n8k8.row.col.f32.tf32.tf32.f32 "
                 "{%0,%1,%2,%3}, {%4,%5,%6,%7}, {%8,%9}, {%0,%1,%2,%3};"
                 : "+f"(d[0]), "+f"(d[1]), "+f"(d[2]), "+f"(d[3])
                 : "r"(a[0]), "r"(a[1]), "r"(a[2]), "r"(a[3]), "r"(b[0]), "r"(b[1]));
}

template <int EPI>   // 0 bias, 1 bias+res, 2 bias+gelu
__global__ __launch_bounds__(256)
void tf32gemm(const float* __restrict__ A, const float* __restrict__ B,
              const float* __restrict__ bias, const float* __restrict__ res,
              float* __restrict__ C, int M, int N, int K,
              int lda, int ldb, int ldc) {
    __shared__ float As[128][36];   // row-major tile, pad 4
    __shared__ float Bs[32][132];   // k-major tile, pad 4

    int tid = threadIdx.x;
    int row0 = blockIdx.y * 128, col0 = blockIdx.x * 128;

    int arow = tid >> 3;            // 0..31 (+32*i)
    int acol = (tid & 7) * 4;       // 0..28
    int brow = tid >> 5;            // 0..7 (+8*p)
    int bcol = (tid & 31) * 4;      // 0..124

    int lane = tid & 31, wid = tid >> 5;
    int wm = (wid >> 2) * 64, wn = (wid & 3) * 32;
    int g = lane >> 2, t = lane & 3;

    float acc[16][4];
    #pragma unroll
    for (int i = 0; i < 16; i++)
        #pragma unroll
        for (int j = 0; j < 4; j++) acc[i][j] = 0.f;

    float4 ra[4], rb[4];

    // prefetch first tile
    #pragma unroll
    for (int i = 0; i < 4; i++)
        ra[i] = *(const float4*)(A + (size_t)(row0 + arow + i * 32) * lda + acol);
    #pragma unroll
    for (int p = 0; p < 4; p++)
        rb[p] = *(const float4*)(B + (size_t)(brow + p * 8) * ldb + col0 + bcol);

    for (int k0 = 0; k0 < K; k0 += 32) {
        // store (tf32-rounded) to smem
        #pragma unroll
        for (int i = 0; i < 4; i++) {
            As[arow + i * 32][acol + 0] = __uint_as_float(f2tf32(ra[i].x));
            As[arow + i * 32][acol + 1] = __uint_as_float(f2tf32(ra[i].y));
            As[arow + i * 32][acol + 2] = __uint_as_float(f2tf32(ra[i].z));
            As[arow + i * 32][acol + 3] = __uint_as_float(f2tf32(ra[i].w));
        }
        #pragma unroll
        for (int p = 0; p < 4; p++) {
            Bs[brow + p * 8][bcol + 0] = __uint_as_float(f2tf32(rb[p].x));
            Bs[brow + p * 8][bcol + 1] = __uint_as_float(f2tf32(rb[p].y));
            Bs[brow + p * 8][bcol + 2] = __uint_as_float(f2tf32(rb[p].z));
            Bs[brow + p * 8][bcol + 3] = __uint_as_float(f2tf32(rb[p].w));
        }
        __syncthreads();

        // prefetch next tile (overlaps with mma below)
        if (k0 + 32 < K) {
            #pragma unroll
            for (int i = 0; i < 4; i++)
                ra[i] = *(const float4*)(A + (size_t)(row0 + arow + i * 32) * lda + k0 + 32 + acol);
            #pragma unroll
            for (int p = 0; p < 4; p++)
                rb[p] = *(const float4*)(B + (size_t)(k0 + 32 + brow + p * 8) * ldb + col0 + bcol);
        }

        #pragma unroll
        for (int ks = 0; ks < 4; ks++) {
            int k = ks * 8;
            uint32_t afr[4][4], bfr[4][2];
            #pragma unroll
            for (int mi = 0; mi < 4; mi++) {
                int r = wm + mi * 16 + g;
                afr[mi][0] = __float_as_uint(As[r][k + t]);
                afr[mi][1] = __float_as_uint(As[r + 8][k + t]);
                afr[mi][2] = __float_as_uint(As[r][k + t + 4]);
                afr[mi][3] = __float_as_uint(As[r + 8][k + t + 4]);
            }
            #pragma unroll
            for (int ni = 0; ni < 4; ni++) {
                int c = wn + ni * 8 + g;
                bfr[ni][0] = __float_as_uint(Bs[k + t][c]);
                bfr[ni][1] = __float_as_uint(Bs[k + t + 4][c]);
            }
            #pragma unroll
            for (int mi = 0; mi < 4; mi++)
                #pragma unroll
                for (int ni = 0; ni < 4; ni++)
                    mma_tf32(acc[mi * 4 + ni], afr[mi], bfr[ni]);
        }
        __syncthreads();
    }

    // epilogue
    #pragma unroll
    for (int mi = 0; mi < 4; mi++) {
        #pragma unroll
        for (int ni = 0; ni < 4; ni++) {
            int r = row0 + wm + mi * 16 + g;
            int c = col0 + wn + ni * 8 + t * 2;
            float b0 = bias[c], b1 = bias[c + 1];
            float v0 = acc[mi * 4 + ni][0] + b0;
            float v1 = acc[mi * 4 + ni][1] + b1;
            float v2 = acc[mi * 4 + ni][2] + b0;
            float v3 = acc[mi * 4 + ni][3] + b1;
            if (EPI == 1) {
                v0 += res[(size_t)r * ldc + c];
                v1 += res[(size_t)r * ldc + c + 1];
                v2 += res[(size_t)(r + 8) * ldc + c];
                v3 += res[(size_t)(r + 8) * ldc + c + 1];
            }
            if (EPI == 2) {
                v0 = 0.5f * v0 * (1.0f + erff(v0 * 0.70710678118654752f));
                v1 = 0.5f * v1 * (1.0f + erff(v1 * 0.70710678118654752f));
                v2 = 0.5f * v2 * (1.0f + erff(v2 * 0.70710678118654752f));
                v3 = 0.5f * v3 * (1.0f + erff(v3 * 0.70710678118654752f));
            }
            *(float2*)(C + (size_t)r * ldc + c) = make_float2(v0, v1);
            *(float2*)(C + (size_t)(r + 8) * ldc + c) = make_float2(v2, v3);
        }
    }
}

// ---------------- scatter qkv: c[4096,3072] -> q scratch + present out -----
__global__ void scatter_qkv(const float* __restrict__ c, float* __restrict__ q,
                            float* __restrict__ present) {
    int idx = blockIdx.x * blockDim.x + threadIdx.x;
    if (idx >= Bz * Sz * 3 * Dz) return;
    int row = idx / (3 * Dz);
    int col = idx - row * (3 * Dz);
    int b = row >> 11, s = row & (Sz - 1);
    int which = col >> 10;
    int rest = col & (Dz - 1);
    int h = rest >> 6, d = rest & 63;
    float val = c[idx];
    if (which == 0)
        q[(((size_t)(b * Hz + h) * Sz + s) * HDz) + d] = val;
    else
        present[(((size_t)((b * 2 + (which - 1)) * Hz + h) * Sz + s) * HDz) + d] = val;
}

// ---------------- scores: W = scale * Q @ K^T (NT), per (b,h) --------------
__global__ void scores_k(const float* __restrict__ q, const float* __restrict__ present,
                         float* __restrict__ w) {
    int bh = blockIdx.z;
    int row0 = blockIdx.y * 64, col0 = blockIdx.x * 64;
    if (col0 > row0 + 63) return;               // fully masked block
    int b = bh >> 4, h = bh & 15;
    const float* Q  = q + (size_t)bh * Sz * HDz;
    const float* Kd = present + (size_t)((b * 2) * Hz + h) * Sz * HDz;
    float* W = w + (size_t)bh * Sz * Sz;

    __shared__ float Qs[64][65];
    __shared__ float Ks[64][65];
    int tid = threadIdx.x;
    int r = tid >> 4, c4 = (tid & 15) * 4;
    #pragma unroll
    for (int rr = r; rr < 64; rr += 16) {
        float4 a = *(const float4*)(Q + (size_t)(row0 + rr) * HDz + c4);
        Qs[rr][c4 + 0] = a.x; Qs[rr][c4 + 1] = a.y; Qs[rr][c4 + 2] = a.z; Qs[rr][c4 + 3] = a.w;
        float4 k4 = *(const float4*)(Kd + (size_t)(col0 + rr) * HDz + c4);
        Ks[rr][c4 + 0] = k4.x; Ks[rr][c4 + 1] = k4.y; Ks[rr][c4 + 2] = k4.z; Ks[rr][c4 + 3] = k4.w;
    }
    __syncthreads();

    int tx = tid & 15, ty = tid >> 4;
    float acc[4][4];
    #pragma unroll
    for (int i = 0; i < 4; i++)
        #pragma unroll
        for (int j = 0; j < 4; j++) acc[i][j] = 0.f;

    #pragma unroll
    for (int d = 0; d < 64; d++) {
        float ra[4], rb[4];
        #pragma unroll
        for (int i = 0; i < 4; i++) ra[i] = Qs[ty * 4 + i][d];
        #pragma unroll
        for (int j = 0; j < 4; j++) rb[j] = Ks[tx * 4 + j][d];
        #pragma unroll
        for (int i = 0; i < 4; i++)
            #pragma unroll
            for (int j = 0; j < 4; j++) acc[i][j] = fmaf(ra[i], rb[j], acc[i][j]);
    }
    #pragma unroll
    for (int i = 0; i < 4; i++)
        #pragma unroll
        for (int j = 0; j < 4; j++)
            W[(size_t)(row0 + ty * 4 + i) * Sz + col0 + tx * 4 + j] = acc[i][j] * 0.125f;
}

// ---------------- causal softmax, in place on w ----------------------------
__global__ void softmax_causal(float* __restrict__ w) {
    int row = blockIdx.x;
    int bh  = blockIdx.y;
    float* wr = w + ((size_t)bh * Sz + row) * Sz;
    int n = row + 1;
    int tid = threadIdx.x;
    __shared__ float sh[8];
    int lane = tid & 31, wid = tid >> 5;

    float m = -1e30f;
    for (int j = tid; j < n; j += 256) m = fmaxf(m, wr[j]);
    for (int o = 16; o; o >>= 1) m = fmaxf(m, __shfl_xor_sync(0xffffffffu, m, o));
    if (lane == 0) sh[wid] = m;
    __syncthreads();
    float M = -1e30f;
    #pragma unroll
    for (int i = 0; i < 8; i++) M = fmaxf(M, sh[i]);
    __syncthreads();

    float s = 0.f;
    for (int j = tid; j < n; j += 256) s += expf(wr[j] - M);
    for (int o = 16; o; o >>= 1) s += __shfl_xor_sync(0xffffffffu, s, o);
    if (lane == 0) sh[wid] = s;
    __syncthreads();
    float Ssum = 0.f;
    #pragma unroll
    for (int i = 0; i < 8; i++) Ssum += sh[i];
    float inv = 1.0f / Ssum;

    for (int j = tid; j < Sz; j += 256)
        wr[j] = (j < n) ? expf(wr[j] - M) * inv : 0.0f;
}

// ---------------- A = W @ V per (b,h), causal K trimming -------------------
__global__ void av_gemm(const float* __restrict__ w, const float* __restrict__ present,
                        float* __restrict__ a) {
    int bh = blockIdx.z;
    int b = bh >> 4, h = bh & 15;
    int row0 = blockIdx.y * 64;
    const float* W = w + (size_t)bh * Sz * Sz;
    const float* V = present + (size_t)((b * 2 + 1) * Hz + h) * Sz * HDz;
    float* A = a + ((size_t)b * Sz) * Dz + h * HDz;

    __shared__ float Ws[16][65];
    __shared__ float Vs[16][64];
    int tid = threadIdx.x;
    int aR = tid >> 2, aC = (tid & 3) * 4;      // 64 x 16 tile of W
    int bR = tid >> 4, bC = (tid & 15) * 4;     // 16 x 64 tile of V
    int tx = tid & 15, ty = tid >> 4;

    float acc[4][4];
    #pragma unroll
    for (int i = 0; i < 4; i++)
        #pragma unroll
        for (int j = 0; j < 4; j++) acc[i][j] = 0.f;

    int kEnd = row0 + 64;                       // w[row, k>row] == 0 (causal)
    for (int k0 = 0; k0 < kEnd; k0 += 16) {
        float4 wv = *(const float4*)(W + (size_t)(row0 + aR) * Sz + k0 + aC);
        Ws[aC + 0][aR] = wv.x; Ws[aC + 1][aR] = wv.y; Ws[aC + 2][aR] = wv.z; Ws[aC + 3][aR] = wv.w;
        *(float4*)&Vs[bR][bC] = *(const float4*)(V + (size_t)(k0 + bR) * HDz + bC);
        __syncthreads();
        #pragma unroll
        for (int k = 0; k < 16; k++) {
            float ra[4], rb[4];
            #pragma unroll
            for (int i = 0; i < 4; i++) ra[i] = Ws[k][ty * 4 + i];
            #pragma unroll
            for (int j = 0; j < 4; j++) rb[j] = Vs[k][tx * 4 + j];
            #pragma unroll
            for (int i = 0; i < 4; i++)
                #pragma unroll
                for (int j = 0; j < 4; j++) acc[i][j] = fmaf(ra[i], rb[j], acc[i][j]);
        }
        __syncthreads();
    }
    #pragma unroll
    for (int i = 0; i < 4; i++)
        #pragma unroll
        for (int j = 0; j < 4; j++)
            A[(size_t)(row0 + ty * 4 + i) * Dz + tx * 4 + j] = acc[i][j];
}

// ---------------- host ------------------------------------------------------
extern "C" void kernel_launch(void* const* d_in, const int* in_sizes, int n_in,
                              void* d_out, int out_size) {
    const float* x       = (const float*)d_in[0];
    const float* qkv_w   = (const float*)d_in[1];
    const float* qkv_b   = (const float*)d_in[2];
    const float* merge_w = (const float*)d_in[3];
    const float* merge_b = (const float*)d_in[4];
    const float* mlp1_w  = (const float*)d_in[5];
    const float* mlp1_b  = (const float*)d_in[6];
    const float* mlp2_w  = (const float*)d_in[7];
    const float* mlp2_b  = (const float*)d_in[8];
    const float* n1_g    = (const float*)d_in[9];
    const float* n1_b    = (const float*)d_in[10];
    const float* n2_g    = (const float*)d_in[11];
    const float* n2_b    = (const float*)d_in[12];

    float *ln, *c, *q, *a, *xa, *h1;
    cudaGetSymbolAddress((void**)&ln, g_ln);
    cudaGetSymbolAddress((void**)&c,  g_c);
    cudaGetSymbolAddress((void**)&q,  g_q);
    cudaGetSymbolAddress((void**)&a,  g_a);
    cudaGetSymbolAddress((void**)&xa, g_xa);
    cudaGetSymbolAddress((void**)&h1, g_h1);

    float* out     = (float*)d_out;
    float* xm      = out;                                   // [B,S,D]
    float* present = out + (size_t)Bz * Sz * Dz;            // [B,2,H,S,hd]
    float* w       = present + (size_t)Bz * 2 * Hz * Sz * HDz; // [B,H,S,S]

    const int M = Bz * Sz;   // 4096

    // 1) ln1
    layernorm_k<<<M, 256>>>(x, n1_g, n1_b, ln);
    // 2) qkv gemm (tf32 tensor cores)
    tf32gemm<0><<<dim3(3 * Dz / 128, M / 128), 256>>>(ln, qkv_w, qkv_b, nullptr, c,
                                                      M, 3 * Dz, Dz, Dz, 3 * Dz, 3 * Dz);
    // 3) scatter q -> scratch, k/v -> present (output)
    scatter_qkv<<<(M * 3 * Dz) / 256, 256>>>(c, q, present);
    // 4) scores (causal-trimmed) -> w region
    scores_k<<<dim3(Sz / 64, Sz / 64, Bz * Hz), 256>>>(q, present, w);
    // 5) causal softmax in place on w
    softmax_causal<<<dim3(Sz, Bz * Hz), 256>>>(w);
    // 6) attn out = w @ v  -> g_a in [B,S,D] layout
    av_gemm<<<dim3(1, Sz / 64, Bz * Hz), 256>>>(w, present, a);
    // 7) merge gemm + residual -> xa
    tf32gemm<1><<<dim3(Dz / 128, M / 128), 256>>>(a, merge_w, merge_b, x, xa,
                                                  M, Dz, Dz, Dz, Dz, Dz);
    // 8) ln2
    layernorm_k<<<M, 256>>>(xa, n2_g, n2_b, ln);
    // 9) mlp1 + gelu (tf32)
    tf32gemm<2><<<dim3(4 * Dz / 128, M / 128), 256>>>(ln, mlp1_w, mlp1_b, nullptr, h1,
                                                      M, 4 * Dz, Dz, Dz, 4 * Dz, 4 * Dz);
    // 10) mlp2 + residual -> xm (output, tf32)
    tf32gemm<1><<<dim3(Dz / 128, M / 128), 256>>>(h1, mlp2_w, mlp2_b, xa, xm,
                                                  M, Dz, 4 * Dz, 4 * Dz, Dz, Dz);
}

// round 3
// speedup vs baseline: 2.7892x; 1.3632x over previous
#include <cuda_runtime.h>
#include <math.h>
#include <stdint.h>

#define Bz 2
#define Sz 2048
#define Dz 1024
#define Hz 16
#define HDz 64

// ---------------- scratch (device globals; no allocation allowed) ----------
__device__ float g_ln[Bz * Sz * Dz];            // layernorm output (reused)
__device__ float g_q[Bz * Hz * Sz * HDz];       // q in [B,H,S,hd]
__device__ float g_a[Bz * Sz * Dz];             // attention output in [B,S,D]
__device__ float g_xa[Bz * Sz * Dz];            // x + attn
__device__ float g_h1[Bz * Sz * 4 * Dz];        // mlp hidden

// ---------------- helpers ---------------------------------------------------
__device__ __forceinline__ uint32_t f2tf32(float x) {
    uint32_t y;
    asm("cvt.rna.tf32.f32 %0, %1;" : "=r"(y) : "f"(x));
    return y;
}
__device__ __forceinline__ void mma_tf32(float (&d)[4], const uint32_t (&a)[4], const uint32_t (&b)[2]) {
    asm volatile("mma.sync.aligned.m16n8k8.row.col.f32.tf32.tf32.f32 "
                 "{%0,%1,%2,%3}, {%4,%5,%6,%7}, {%8,%9}, {%0,%1,%2,%3};"
                 : "+f"(d[0]), "+f"(d[1]), "+f"(d[2]), "+f"(d[3])
                 : "r"(a[0]), "r"(a[1]), "r"(a[2]), "r"(a[3]), "r"(b[0]), "r"(b[1]));
}

// ---------------- layernorm: one block per row, D=1024 ---------------------
__global__ void layernorm_k(const float* __restrict__ x, const float* __restrict__ g,
                            const float* __restrict__ b, float* __restrict__ y) {
    int row = blockIdx.x;
    int tid = threadIdx.x;                       // 256 threads
    const float4* xr = (const float4*)(x + (size_t)row * Dz);
    float4 v = xr[tid];
    float s  = v.x + v.y + v.z + v.w;
    float sq = v.x * v.x + v.y * v.y + v.z * v.z + v.w * v.w;

    __shared__ float shs[8], shq[8];
    for (int o = 16; o; o >>= 1) { s += __shfl_xor_sync(0xffffffffu, s, o); sq += __shfl_xor_sync(0xffffffffu, sq, o); }
    int lane = tid & 31, wid = tid >> 5;
    if (lane == 0) { shs[wid] = s; shq[wid] = sq; }
    __syncthreads();
    float ts = 0.f, tq = 0.f;
    #pragma unroll
    for (int i = 0; i < 8; i++) { ts += shs[i]; tq += shq[i]; }
    float mean = ts * (1.0f / Dz);
    float var  = tq * (1.0f / Dz) - mean * mean;
    float rstd = rsqrtf(var + 1e-5f);

    float4 gg = ((const float4*)g)[tid];
    float4 bb = ((const float4*)b)[tid];
    float4 o;
    o.x = (v.x - mean) * rstd * gg.x + bb.x;
    o.y = (v.y - mean) * rstd * gg.y + bb.y;
    o.z = (v.z - mean) * rstd * gg.z + bb.z;
    o.w = (v.w - mean) * rstd * gg.w + bb.w;
    ((float4*)(y + (size_t)row * Dz))[tid] = o;
}

// ---------------- tf32 tensor-core GEMM ------------------------------------
// EPI: 0 bias, 1 bias+res, 2 bias+gelu, 3 bias + scatter to q/present
__device__ __forceinline__ void wqkv(float* __restrict__ q, float* __restrict__ pres,
                                     int r, int c, float v) {
    int b = r >> 11, s = r & (Sz - 1);
    int which = c >> 10, rest = c & (Dz - 1);
    int h = rest >> 6, d = rest & 63;
    if (which == 0)
        q[(((size_t)(b * Hz + h) * Sz + s) * HDz) + d] = v;
    else
        pres[(((size_t)((b * 2 + (which - 1)) * Hz + h) * Sz + s) * HDz) + d] = v;
}

template <int EPI>
__global__ __launch_bounds__(256)
void tf32gemm(const float* __restrict__ A, const float* __restrict__ B,
              const float* __restrict__ bias, const float* __restrict__ res,
              float* __restrict__ C, float* __restrict__ qp, float* __restrict__ pp,
              int M, int N, int K, int lda, int ldb, int ldc) {
    __shared__ float As[128][36];
    __shared__ float Bs[32][132];

    int tid = threadIdx.x;
    int row0 = blockIdx.y * 128, col0 = blockIdx.x * 128;

    int arow = tid >> 3;            // 0..31 (+32*i)
    int acol = (tid & 7) * 4;
    int brow = tid >> 5;            // 0..7 (+8*p)
    int bcol = (tid & 31) * 4;

    int lane = tid & 31, wid = tid >> 5;
    int wm = (wid >> 2) * 64, wn = (wid & 3) * 32;
    int g = lane >> 2, t = lane & 3;

    float acc[16][4];
    #pragma unroll
    for (int i = 0; i < 16; i++)
        #pragma unroll
        for (int j = 0; j < 4; j++) acc[i][j] = 0.f;

    float4 ra[4], rb[4];
    #pragma unroll
    for (int i = 0; i < 4; i++)
        ra[i] = *(const float4*)(A + (size_t)(row0 + arow + i * 32) * lda + acol);
    #pragma unroll
    for (int p = 0; p < 4; p++)
        rb[p] = *(const float4*)(B + (size_t)(brow + p * 8) * ldb + col0 + bcol);

    for (int k0 = 0; k0 < K; k0 += 32) {
        #pragma unroll
        for (int i = 0; i < 4; i++) {
            As[arow + i * 32][acol + 0] = __uint_as_float(f2tf32(ra[i].x));
            As[arow + i * 32][acol + 1] = __uint_as_float(f2tf32(ra[i].y));
            As[arow + i * 32][acol + 2] = __uint_as_float(f2tf32(ra[i].z));
            As[arow + i * 32][acol + 3] = __uint_as_float(f2tf32(ra[i].w));
        }
        #pragma unroll
        for (int p = 0; p < 4; p++) {
            Bs[brow + p * 8][bcol + 0] = __uint_as_float(f2tf32(rb[p].x));
            Bs[brow + p * 8][bcol + 1] = __uint_as_float(f2tf32(rb[p].y));
            Bs[brow + p * 8][bcol + 2] = __uint_as_float(f2tf32(rb[p].z));
            Bs[brow + p * 8][bcol + 3] = __uint_as_float(f2tf32(rb[p].w));
        }
        __syncthreads();

        if (k0 + 32 < K) {
            #pragma unroll
            for (int i = 0; i < 4; i++)
                ra[i] = *(const float4*)(A + (size_t)(row0 + arow + i * 32) * lda + k0 + 32 + acol);
            #pragma unroll
            for (int p = 0; p < 4; p++)
                rb[p] = *(const float4*)(B + (size_t)(k0 + 32 + brow + p * 8) * ldb + col0 + bcol);
        }

        #pragma unroll
        for (int ks = 0; ks < 4; ks++) {
            int k = ks * 8;
            uint32_t afr[4][4], bfr[4][2];
            #pragma unroll
            for (int mi = 0; mi < 4; mi++) {
                int r = wm + mi * 16 + g;
                afr[mi][0] = __float_as_uint(As[r][k + t]);
                afr[mi][1] = __float_as_uint(As[r + 8][k + t]);
                afr[mi][2] = __float_as_uint(As[r][k + t + 4]);
                afr[mi][3] = __float_as_uint(As[r + 8][k + t + 4]);
            }
            #pragma unroll
            for (int ni = 0; ni < 4; ni++) {
                int c = wn + ni * 8 + g;
                bfr[ni][0] = __float_as_uint(Bs[k + t][c]);
                bfr[ni][1] = __float_as_uint(Bs[k + t + 4][c]);
            }
            #pragma unroll
            for (int mi = 0; mi < 4; mi++)
                #pragma unroll
                for (int ni = 0; ni < 4; ni++)
                    mma_tf32(acc[mi * 4 + ni], afr[mi], bfr[ni]);
        }
        __syncthreads();
    }

    #pragma unroll
    for (int mi = 0; mi < 4; mi++) {
        #pragma unroll
        for (int ni = 0; ni < 4; ni++) {
            int r = row0 + wm + mi * 16 + g;
            int c = col0 + wn + ni * 8 + t * 2;
            float b0 = bias[c], b1 = bias[c + 1];
            float v0 = acc[mi * 4 + ni][0] + b0;
            float v1 = acc[mi * 4 + ni][1] + b1;
            float v2 = acc[mi * 4 + ni][2] + b0;
            float v3 = acc[mi * 4 + ni][3] + b1;
            if (EPI == 1) {
                v0 += res[(size_t)r * ldc + c];
                v1 += res[(size_t)r * ldc + c + 1];
                v2 += res[(size_t)(r + 8) * ldc + c];
                v3 += res[(size_t)(r + 8) * ldc + c + 1];
            }
            if (EPI == 2) {
                v0 = 0.5f * v0 * (1.0f + erff(v0 * 0.70710678118654752f));
                v1 = 0.5f * v1 * (1.0f + erff(v1 * 0.70710678118654752f));
                v2 = 0.5f * v2 * (1.0f + erff(v2 * 0.70710678118654752f));
                v3 = 0.5f * v3 * (1.0f + erff(v3 * 0.70710678118654752f));
            }
            if (EPI == 3) {
                wqkv(qp, pp, r, c, v0);
                wqkv(qp, pp, r, c + 1, v1);
                wqkv(qp, pp, r + 8, c, v2);
                wqkv(qp, pp, r + 8, c + 1, v3);
            } else {
                *(float2*)(C + (size_t)r * ldc + c) = make_float2(v0, v1);
                *(float2*)(C + (size_t)(r + 8) * ldc + c) = make_float2(v2, v3);
            }
        }
    }
}

// ---------------- scores via tf32 mma: W = 0.125 * Q @ K^T -----------------
// 128x128 C tile per block; lower-triangle blocks only. Dynamic smem.
#define QS(r, c) sQ[(r) * 68 + (c)]
#define KS(d, j) sK[(d) * 133 + (j)]
__global__ __launch_bounds__(256)
void scores_mma(const float* __restrict__ q, const float* __restrict__ present,
                float* __restrict__ w) {
    int row0 = blockIdx.y * 128, col0 = blockIdx.x * 128;
    if (col0 > row0 + 127) return;
    int bh = blockIdx.z;
    int b = bh >> 4, h = bh & 15;
    const float* Q  = q + (size_t)bh * Sz * HDz;
    const float* Kd = present + (size_t)((b * 2) * Hz + h) * Sz * HDz;
    float* W = w + (size_t)bh * Sz * Sz;

    extern __shared__ float smem[];
    float* sQ = smem;                 // [128][68]
    float* sK = smem + 128 * 68;      // [64][133] transposed: [d][j]

    int tid = threadIdx.x;
    int lr = tid >> 4;                // 0..15
    int c4 = (tid & 15) * 4;          // 0..60
    #pragma unroll
    for (int i = 0; i < 8; i++) {
        int r = lr + i * 16;
        float4 a = *(const float4*)(Q + (size_t)(row0 + r) * HDz + c4);
        QS(r, c4 + 0) = __uint_as_float(f2tf32(a.x));
        QS(r, c4 + 1) = __uint_as_float(f2tf32(a.y));
        QS(r, c4 + 2) = __uint_as_float(f2tf32(a.z));
        QS(r, c4 + 3) = __uint_as_float(f2tf32(a.w));
        float4 kk = *(const float4*)(Kd + (size_t)(col0 + r) * HDz + c4);
        KS(c4 + 0, r) = __uint_as_float(f2tf32(kk.x));
        KS(c4 + 1, r) = __uint_as_float(f2tf32(kk.y));
        KS(c4 + 2, r) = __uint_as_float(f2tf32(kk.z));
        KS(c4 + 3, r) = __uint_as_float(f2tf32(kk.w));
    }
    __syncthreads();

    int lane = tid & 31, wid = tid >> 5;
    int wm = (wid >> 2) * 64, wn = (wid & 3) * 32;
    int g = lane >> 2, t = lane & 3;

    float acc[16][4];
    #pragma unroll
    for (int i = 0; i < 16; i++)
        #pragma unroll
        for (int j = 0; j < 4; j++) acc[i][j] = 0.f;

    #pragma unroll
    for (int ks = 0; ks < 8; ks++) {
        int k = ks * 8;
        uint32_t afr[4][4], bfr[4][2];
        #pragma unroll
        for (int mi = 0; mi < 4; mi++) {
            int r = wm + mi * 16 + g;
            afr[mi][0] = __float_as_uint(QS(r, k + t));
            afr[mi][1] = __float_as_uint(QS(r + 8, k + t));
            afr[mi][2] = __float_as_uint(QS(r, k + t + 4));
            afr[mi][3] = __float_as_uint(QS(r + 8, k + t + 4));
        }
        #pragma unroll
        for (int ni = 0; ni < 4; ni++) {
            int c = wn + ni * 8 + g;
            bfr[ni][0] = __float_as_uint(KS(k + t, c));
            bfr[ni][1] = __float_as_uint(KS(k + t + 4, c));
        }
        #pragma unroll
        for (int mi = 0; mi < 4; mi++)
            #pragma unroll
            for (int ni = 0; ni < 4; ni++)
                mma_tf32(acc[mi * 4 + ni], afr[mi], bfr[ni]);
    }

    #pragma unroll
    for (int mi = 0; mi < 4; mi++) {
        #pragma unroll
        for (int ni = 0; ni < 4; ni++) {
            int r = row0 + wm + mi * 16 + g;
            int c = col0 + wn + ni * 8 + t * 2;
            *(float2*)(W + (size_t)r * Sz + c) =
                make_float2(acc[mi * 4 + ni][0] * 0.125f, acc[mi * 4 + ni][1] * 0.125f);
            *(float2*)(W + (size_t)(r + 8) * Sz + c) =
                make_float2(acc[mi * 4 + ni][2] * 0.125f, acc[mi * 4 + ni][3] * 0.125f);
        }
    }
}

// ---------------- causal softmax, row cached in registers ------------------
__global__ __launch_bounds__(256)
void softmax_reg(float* __restrict__ w) {
    int row = blockIdx.x;
    int bh  = blockIdx.y;
    float* wr = w + ((size_t)bh * Sz + row) * Sz;
    int n = row + 1;
    int tid = threadIdx.x;
    int lane = tid & 31, wid = tid >> 5;
    __shared__ float sh[8];

    float4 v0 = ((const float4*)wr)[tid];
    float4 v1 = ((const float4*)wr)[tid + 256];
    int j0 = tid * 4, j1 = (tid + 256) * 4;

    float m = -1e30f;
    m = (j0 + 0 < n) ? fmaxf(m, v0.x) : m;
    m = (j0 + 1 < n) ? fmaxf(m, v0.y) : m;
    m = (j0 + 2 < n) ? fmaxf(m, v0.z) : m;
    m = (j0 + 3 < n) ? fmaxf(m, v0.w) : m;
    m = (j1 + 0 < n) ? fmaxf(m, v1.x) : m;
    m = (j1 + 1 < n) ? fmaxf(m, v1.y) : m;
    m = (j1 + 2 < n) ? fmaxf(m, v1.z) : m;
    m = (j1 + 3 < n) ? fmaxf(m, v1.w) : m;
    for (int o = 16; o; o >>= 1) m = fmaxf(m, __shfl_xor_sync(0xffffffffu, m, o));
    if (lane == 0) sh[wid] = m;
    __syncthreads();
    float M = -1e30f;
    #pragma unroll
    for (int i = 0; i < 8; i++) M = fmaxf(M, sh[i]);
    __syncthreads();

    float4 p0, p1;
    p0.x = (j0 + 0 < n) ? __expf(v0.x - M) : 0.f;
    p0.y = (j0 + 1 < n) ? __expf(v0.y - M) : 0.f;
    p0.z = (j0 + 2 < n) ? __expf(v0.z - M) : 0.f;
    p0.w = (j0 + 3 < n) ? __expf(v0.w - M) : 0.f;
    p1.x = (j1 + 0 < n) ? __expf(v1.x - M) : 0.f;
    p1.y = (j1 + 1 < n) ? __expf(v1.y - M) : 0.f;
    p1.z = (j1 + 2 < n) ? __expf(v1.z - M) : 0.f;
    p1.w = (j1 + 3 < n) ? __expf(v1.w - M) : 0.f;

    float s = p0.x + p0.y + p0.z + p0.w + p1.x + p1.y + p1.z + p1.w;
    for (int o = 16; o; o >>= 1) s += __shfl_xor_sync(0xffffffffu, s, o);
    if (lane == 0) sh[wid] = s;
    __syncthreads();
    float S = 0.f;
    #pragma unroll
    for (int i = 0; i < 8; i++) S += sh[i];
    float inv = 1.0f / S;

    p0.x *= inv; p0.y *= inv; p0.z *= inv; p0.w *= inv;
    p1.x *= inv; p1.y *= inv; p1.z *= inv; p1.w *= inv;
    ((float4*)wr)[tid] = p0;
    ((float4*)wr)[tid + 256] = p1;
}

// ---------------- A = W @ V via tf32 mma, causal K-trim --------------------
__global__ __launch_bounds__(256)
void av_mma(const float* __restrict__ w, const float* __restrict__ present,
            float* __restrict__ a) {
    int bh = blockIdx.z;
    int b = bh >> 4, h = bh & 15;
    int row0 = blockIdx.y * 128;
    const float* W = w + (size_t)bh * Sz * Sz;
    const float* V = present + (size_t)((b * 2 + 1) * Hz + h) * Sz * HDz;
    float* A = a + ((size_t)b * Sz) * Dz + h * HDz;

    __shared__ float Ws[128][36];
    __shared__ float Vs[32][68];

    int tid = threadIdx.x;
    int wrow = tid >> 3, wcol = (tid & 7) * 4;       // W tile loader
    int vrow = tid >> 4, vcol = (tid & 15) * 4;      // V tile loader
    int lane = tid & 31, wid = tid >> 5;
    int wm = (wid >> 1) * 32, wn = (wid & 1) * 32;
    int g = lane >> 2, t = lane & 3;

    float acc[8][4];
    #pragma unroll
    for (int i = 0; i < 8; i++)
        #pragma unroll
        for (int j = 0; j < 4; j++) acc[i][j] = 0.f;

    int kEnd = row0 + 128;
    for (int k0 = 0; k0 < kEnd; k0 += 32) {
        #pragma unroll
        for (int i = 0; i < 4; i++) {
            int r = wrow + i * 32;
            float4 wv = *(const float4*)(W + (size_t)(row0 + r) * Sz + k0 + wcol);
            Ws[r][wcol + 0] = __uint_as_float(f2tf32(wv.x));
            Ws[r][wcol + 1] = __uint_as_float(f2tf32(wv.y));
            Ws[r][wcol + 2] = __uint_as_float(f2tf32(wv.z));
            Ws[r][wcol + 3] = __uint_as_float(f2tf32(wv.w));
        }
        #pragma unroll
        for (int i = 0; i < 2; i++) {
            int r = vrow + i * 16;
            float4 vv = *(const float4*)(V + (size_t)(k0 + r) * HDz + vcol);
            Vs[r][vcol + 0] = __uint_as_float(f2tf32(vv.x));
            Vs[r][vcol + 1] = __uint_as_float(f2tf32(vv.y));
            Vs[r][vcol + 2] = __uint_as_float(f2tf32(vv.z));
            Vs[r][vcol + 3] = __uint_as_float(f2tf32(vv.w));
        }
        __syncthreads();

        #pragma unroll
        for (int ks = 0; ks < 4; ks++) {
            int k = ks * 8;
            uint32_t afr[2][4], bfr[4][2];
            #pragma unroll
            for (int mi = 0; mi < 2; mi++) {
                int r = wm + mi * 16 + g;
                afr[mi][0] = __float_as_uint(Ws[r][k + t]);
                afr[mi][1] = __float_as_uint(Ws[r + 8][k + t]);
                afr[mi][2] = __float_as_uint(Ws[r][k + t + 4]);
                afr[mi][3] = __float_as_uint(Ws[r + 8][k + t + 4]);
            }
            #pragma unroll
            for (int ni = 0; ni < 4; ni++) {
                int c = wn + ni * 8 + g;
                bfr[ni][0] = __float_as_uint(Vs[k + t][c]);
                bfr[ni][1] = __float_as_uint(Vs[k + t + 4][c]);
            }
            #pragma unroll
            for (int mi = 0; mi < 2; mi++)
                #pragma unroll
                for (int ni = 0; ni < 4; ni++)
                    mma_tf32(acc[mi * 4 + ni], afr[mi], bfr[ni]);
        }
        __syncthreads();
    }

    #pragma unroll
    for (int mi = 0; mi < 2; mi++) {
        #pragma unroll
        for (int ni = 0; ni < 4; ni++) {
            int r = row0 + wm + mi * 16 + g;
            int c = wn + ni * 8 + t * 2;
            *(float2*)(A + (size_t)r * Dz + c) =
                make_float2(acc[mi * 4 + ni][0], acc[mi * 4 + ni][1]);
            *(float2*)(A + (size_t)(r + 8) * Dz + c) =
                make_float2(acc[mi * 4 + ni][2], acc[mi * 4 + ni][3]);
        }
    }
}

// ---------------- host ------------------------------------------------------
extern "C" void kernel_launch(void* const* d_in, const int* in_sizes, int n_in,
                              void* d_out, int out_size) {
    const float* x       = (const float*)d_in[0];
    const float* qkv_w   = (const float*)d_in[1];
    const float* qkv_b   = (const float*)d_in[2];
    const float* merge_w = (const float*)d_in[3];
    const float* merge_b = (const float*)d_in[4];
    const float* mlp1_w  = (const float*)d_in[5];
    const float* mlp1_b  = (const float*)d_in[6];
    const float* mlp2_w  = (const float*)d_in[7];
    const float* mlp2_b  = (const float*)d_in[8];
    const float* n1_g    = (const float*)d_in[9];
    const float* n1_b    = (const float*)d_in[10];
    const float* n2_g    = (const float*)d_in[11];
    const float* n2_b    = (const float*)d_in[12];

    float *ln, *q, *a, *xa, *h1;
    cudaGetSymbolAddress((void**)&ln, g_ln);
    cudaGetSymbolAddress((void**)&q,  g_q);
    cudaGetSymbolAddress((void**)&a,  g_a);
    cudaGetSymbolAddress((void**)&xa, g_xa);
    cudaGetSymbolAddress((void**)&h1, g_h1);

    float* out     = (float*)d_out;
    float* xm      = out;                                      // [B,S,D]
    float* present = out + (size_t)Bz * Sz * Dz;               // [B,2,H,S,hd]
    float* w       = present + (size_t)Bz * 2 * Hz * Sz * HDz; // [B,H,S,S]

    const int M = Bz * Sz;   // 4096
    const int scoresSmem = (128 * 68 + 64 * 133) * 4;          // 68864 B
    static int attrSet = 0;
    if (!attrSet) {
        cudaFuncSetAttribute(scores_mma, cudaFuncAttributeMaxDynamicSharedMemorySize, scoresSmem);
        attrSet = 1;
    }

    // 1) ln1
    layernorm_k<<<M, 256>>>(x, n1_g, n1_b, ln);
    // 2) qkv gemm, epilogue scatters directly to q scratch + present (output)
    tf32gemm<3><<<dim3(3 * Dz / 128, M / 128), 256>>>(ln, qkv_w, qkv_b, nullptr, nullptr,
                                                      q, present, M, 3 * Dz, Dz, Dz, 3 * Dz, 3 * Dz);
    // 3) scores (tensor cores, causal-trimmed) -> w region
    scores_mma<<<dim3(Sz / 128, Sz / 128, Bz * Hz), 256, scoresSmem>>>(q, present, w);
    // 4) causal softmax in place on w (register-cached rows)
    softmax_reg<<<dim3(Sz, Bz * Hz), 256>>>(w);
    // 5) attn out = w @ v (tensor cores) -> g_a in [B,S,D] layout
    av_mma<<<dim3(1, Sz / 128, Bz * Hz), 256>>>(w, present, a);
    // 6) merge gemm + residual -> xa
    tf32gemm<1><<<dim3(Dz / 128, M / 128), 256>>>(a, merge_w, merge_b, x, xa, nullptr, nullptr,
                                                  M, Dz, Dz, Dz, Dz, Dz);
    // 7) ln2
    layernorm_k<<<M, 256>>>(xa, n2_g, n2_b, ln);
    // 8) mlp1 + gelu
    tf32gemm<2><<<dim3(4 * Dz / 128, M / 128), 256>>>(ln, mlp1_w, mlp1_b, nullptr, h1, nullptr, nullptr,
                                                      M, 4 * Dz, Dz, Dz, 4 * Dz, 4 * Dz);
    // 9) mlp2 + residual -> xm (output)
    tf32gemm<1><<<dim3(Dz / 128, M / 128), 256>>>(h1, mlp2_w, mlp2_b, xa, xm, nullptr, nullptr,
                                                  M, Dz, 4 * Dz, 4 * Dz, Dz, Dz);
}